// round 9
// baseline (speedup 1.0000x reference)
#include <cuda_runtime.h>
#include <math.h>
#include <stdint.h>

#define T_LEN 200
#define E_DIM 64
#define H1 80
#define H2 40
#define NTHREADS 256
#define NSTRIPES 13        // 208 rows = 13 * 16 (covers T=200)
#define ROWS (16 * NSTRIPES)

#define FS 68              // facts tile stride [208][68]; float4-granule conflict-free

__device__ __forceinline__ float sigm(float x) {
    float t;
    asm("tanh.approx.f32 %0, %1;" : "=f"(t) : "f"(0.5f * x));
    return fmaf(0.5f, t, 0.5f);
}
__device__ __forceinline__ void mma_tf32(float c[4], const uint32_t a[4], const uint32_t b[2]) {
    asm volatile(
        "mma.sync.aligned.m16n8k8.row.col.f32.tf32.tf32.f32 "
        "{%0,%1,%2,%3}, {%4,%5,%6,%7}, {%8,%9}, {%0,%1,%2,%3};"
        : "+f"(c[0]), "+f"(c[1]), "+f"(c[2]), "+f"(c[3])
        : "r"(a[0]), "r"(a[1]), "r"(a[2]), "r"(a[3]), "r"(b[0]), "r"(b[1]));
}
__device__ __forceinline__ void cp_async16(uint32_t smem_addr, const void* gptr) {
    asm volatile("cp.async.cg.shared.global [%0], [%1], 16;" :: "r"(smem_addr), "l"(gptr));
}

// ============================================================================
// MLP for S stripes of 16 rows, sharing every B-fragment load across stripes.
// j-dimension split in halves of 5 to cap live accumulators (acc1 + acc2 <= 80).
// ============================================================================
template <int S>
__device__ __forceinline__ void mlp_stripes(
    const uint32_t* __restrict__ fu,
    const float*    __restrict__ wfr,
    const float*    __restrict__ w2fr,
    const float*    __restrict__ c1sh,
    const float*    __restrict__ b2sh,
    const float*    __restrict__ w3sh,
    float*          __restrict__ scoresh,
    int r0a, int r0b, int g, int tg, int lane)
{
    int r0[2] = { r0a, r0b };
    const int src_lo = (g << 2) + (tg >> 1);
    const int src_hi = src_lo + 2;
    const bool odd = (tg & 1);

    float acc2[S][5][4];
    #pragma unroll
    for (int s = 0; s < S; s++)
        #pragma unroll
        for (int j = 0; j < 5; j++)
            #pragma unroll
            for (int q = 0; q < 4; q++) acc2[s][j][q] = 0.0f;

    #pragma unroll
    for (int half = 0; half < 2; half++) {
        // ---- GEMM1, columns j in [half*5, half*5+5), both stripes ----
        float acc1[S][5][4];
        #pragma unroll
        for (int s = 0; s < S; s++)
            #pragma unroll
            for (int j = 0; j < 5; j++)
                #pragma unroll
                for (int q = 0; q < 4; q++) acc1[s][j][q] = 0.0f;

        #pragma unroll
        for (int kt = 0; kt < 8; kt++) {
            const int k0 = kt * 8 + tg;
            uint32_t a[S][4];
            #pragma unroll
            for (int s = 0; s < S; s++) {
                a[s][0] = fu[(r0[s] + g    ) * FS + k0    ];
                a[s][1] = fu[(r0[s] + g + 8) * FS + k0    ];
                a[s][2] = fu[(r0[s] + g    ) * FS + k0 + 4];
                a[s][3] = fu[(r0[s] + g + 8) * FS + k0 + 4];
            }
            const float2* wp = (const float2*)wfr + kt * 320 + half * 160 + lane;
            #pragma unroll
            for (int j = 0; j < 5; j++) {
                float2 bw = wp[j * 32];
                uint32_t bf[2] = { __float_as_uint(bw.x), __float_as_uint(bw.y) };
                #pragma unroll
                for (int s = 0; s < S; s++) mma_tf32(acc1[s][j], a[s], bf);
            }
        }

        // ---- sigmoid + shfl-exchange + GEMM2 (kt2 = half*5+jj), B shared ----
        #pragma unroll
        for (int jj = 0; jj < 5; jj++) {
            const int kt2 = half * 5 + jj;
            const int n0 = kt2 * 8 + 2 * tg;
            const float c1a = c1sh[n0], c1b = c1sh[n0 + 1];
            uint32_t af[S][4];
            #pragma unroll
            for (int s = 0; s < S; s++) {
                float s0 = sigm(acc1[s][jj][0] + c1a);
                float s1 = sigm(acc1[s][jj][1] + c1b);
                float s2 = sigm(acc1[s][jj][2] + c1a);
                float s3 = sigm(acc1[s][jj][3] + c1b);

                float v0 = __shfl_sync(0xFFFFFFFF, s0, src_lo);
                float v1 = __shfl_sync(0xFFFFFFFF, s1, src_lo);
                float a0 = odd ? v1 : v0;
                v0 = __shfl_sync(0xFFFFFFFF, s2, src_lo);
                v1 = __shfl_sync(0xFFFFFFFF, s3, src_lo);
                float a1 = odd ? v1 : v0;
                v0 = __shfl_sync(0xFFFFFFFF, s0, src_hi);
                v1 = __shfl_sync(0xFFFFFFFF, s1, src_hi);
                float a2 = odd ? v1 : v0;
                v0 = __shfl_sync(0xFFFFFFFF, s2, src_hi);
                v1 = __shfl_sync(0xFFFFFFFF, s3, src_hi);
                float a3 = odd ? v1 : v0;

                af[s][0] = __float_as_uint(a0);
                af[s][1] = __float_as_uint(a1);
                af[s][2] = __float_as_uint(a2);
                af[s][3] = __float_as_uint(a3);
            }
            const float2* wp2 = (const float2*)w2fr + kt2 * 160 + lane;
            #pragma unroll
            for (int j2 = 0; j2 < 5; j2++) {
                float2 bw = wp2[j2 * 32];
                uint32_t bf[2] = { __float_as_uint(bw.x), __float_as_uint(bw.y) };
                #pragma unroll
                for (int s = 0; s < S; s++) mma_tf32(acc2[s][j2], af[s], bf);
            }
        }
    }

    // ---- epilogue: sigmoid, dot W3, quad-reduce, scores -> smem ----
    #pragma unroll
    for (int s = 0; s < S; s++) {
        float s_lo = 0.0f, s_hi = 0.0f;
        #pragma unroll
        for (int j = 0; j < 5; j++) {
            const int n0 = j * 8 + 2 * tg;
            float bb0 = b2sh[n0], bb1 = b2sh[n0 + 1];
            float w30 = w3sh[n0], w31 = w3sh[n0 + 1];
            s_lo += sigm(acc2[s][j][0] + bb0) * w30 + sigm(acc2[s][j][1] + bb1) * w31;
            s_hi += sigm(acc2[s][j][2] + bb0) * w30 + sigm(acc2[s][j][3] + bb1) * w31;
        }
        s_lo += __shfl_xor_sync(0xFFFFFFFF, s_lo, 1);
        s_lo += __shfl_xor_sync(0xFFFFFFFF, s_lo, 2);
        s_hi += __shfl_xor_sync(0xFFFFFFFF, s_hi, 1);
        s_hi += __shfl_xor_sync(0xFFFFFFFF, s_hi, 2);
        if (tg == 0) {   // b3 omitted: constant shift cancels in softmax
            scoresh[r0[s] + g]     = s_lo;
            scoresh[r0[s] + g + 8] = s_hi;
        }
    }
}

// ============================================================================
// Single fused kernel. One CTA per batch.
// ============================================================================
__global__ __launch_bounds__(NTHREADS, 2)
void fused_kernel(const float* __restrict__ query,
                  const float* __restrict__ facts,
                  const int*   __restrict__ mask,
                  const float* __restrict__ W1,
                  const float* __restrict__ b1,
                  const float* __restrict__ W2,
                  const float* __restrict__ b2,
                  const float* __restrict__ W3,
                  float* __restrict__ out)
{
    extern __shared__ float sm[];
    float* fsh     = sm;                  // [208][68] fp32
    float* wfr     = fsh + ROWS * FS;     // [5120] fragment-packed wefft
    float* w2fr    = wfr + 5120;          // [3200] fragment-packed W2
    float* c1sh    = w2fr + 3200;         // [80]
    float* b2sh    = c1sh + H1;           // [40]
    float* w3sh    = b2sh + H2;           // [40]
    float* scoresh = w3sh + H2;           // [208]
    float* red     = scoresh + ROWS;      // [16]
    float* attnsh  = red + 16;            // [208]
    float* outred  = attnsh + ROWS;       // [256]
    float* qsh     = outred + NTHREADS;   // [64]

    const int b    = blockIdx.x;
    const int tid  = threadIdx.x;
    const int w    = tid >> 5;
    const int lane = tid & 31;
    const int g    = lane >> 2;
    const int tg   = lane & 3;

    // ---------------- async facts staging: issue FIRST, consume later ----------
    {
        const float4* fb = (const float4*)(facts + (size_t)b * T_LEN * E_DIM);
        uint32_t fsh_base;
        asm("{ .reg .u64 t; cvta.to.shared.u64 t, %1; cvt.u32.u64 %0, t; }"
            : "=r"(fsh_base) : "l"(fsh));
        for (int i = tid; i < T_LEN * 16; i += NTHREADS) {
            int t = i >> 4, e4 = i & 15;
            cp_async16(fsh_base + (t * FS + e4 * 4) * 4, fb + i);
        }
        asm volatile("cp.async.commit_group;");
    }
    int mbit = 1;
    if (tid < T_LEN) mbit = mask[(size_t)b * T_LEN + tid];

    // zero pad rows [200,208)
    for (int i = tid; i < (ROWS - T_LEN) * 16; i += NTHREADS) {
        int t = T_LEN + (i >> 4), e4 = i & 15;
        *(float4*)&fsh[t * FS + e4 * 4] = make_float4(0.f, 0.f, 0.f, 0.f);
    }

    if (tid < E_DIM) qsh[tid] = query[(size_t)b * E_DIM + tid];
    if (tid < H2)    { b2sh[tid] = b2[tid]; w3sh[tid] = W3[tid]; }
    __syncthreads();    // qsh ready

    // ---------------- per-batch effective layer-1 weights (fragment-packed) ----
    for (int fp = tid; fp < 2560; fp += NTHREADS) {
        int kt = fp / 320, rem = fp - kt * 320;
        int j = rem >> 5, l5 = rem & 31;
        int gg = l5 >> 2, tt = l5 & 3;
        int n = j * 8 + gg;
        int ka = kt * 8 + tt, kb = ka + 4;
        float va = W1[(64 + ka) * H1 + n] - W1[(128 + ka) * H1 + n] + qsh[ka] * W1[(192 + ka) * H1 + n];
        float vb = W1[(64 + kb) * H1 + n] - W1[(128 + kb) * H1 + n] + qsh[kb] * W1[(192 + kb) * H1 + n];
        *(float2*)&wfr[2 * fp] = make_float2(va, vb);
    }
    for (int fp = tid; fp < 1600; fp += NTHREADS) {
        int kt = fp / 160, rem = fp - kt * 160;
        int j = rem >> 5, l5 = rem & 31;
        int gg = l5 >> 2, tt = l5 & 3;
        int n = j * 8 + gg;
        int ka = kt * 8 + tt;
        *(float2*)&w2fr[2 * fp] = make_float2(W2[ka * H2 + n], W2[(ka + 4) * H2 + n]);
    }
    if (tid < H1) {
        float acc = b1[tid];
        #pragma unroll 8
        for (int e = 0; e < E_DIM; e++)
            acc += qsh[e] * (W1[e * H1 + tid] + W1[(128 + e) * H1 + tid]);
        c1sh[tid] = acc;
    }

    asm volatile("cp.async.wait_group 0;");
    __syncthreads();

    const uint32_t* fu = (const uint32_t*)fsh;

    // ---------------- MLP: warps 0-4 take stripe pairs, 5-7 singles ------------
    if (w < 5)
        mlp_stripes<2>(fu, wfr, w2fr, c1sh, b2sh, w3sh, scoresh,
                       16 * w, 16 * (w + 8), g, tg, lane);
    else
        mlp_stripes<1>(fu, wfr, w2fr, c1sh, b2sh, w3sh, scoresh,
                       16 * w, 0, g, tg, lane);
    __syncthreads();

    // ---------------- masked softmax over T (warp-shuffle reductions) ----------
    const float PADV = -4294967295.0f;   // -2^32 + 1
    float v;
    if (tid < T_LEN)
        v = (mbit == 1) ? scoresh[tid] : PADV;
    else
        v = -INFINITY;

    float m = v;
    #pragma unroll
    for (int off = 16; off > 0; off >>= 1)
        m = fmaxf(m, __shfl_xor_sync(0xFFFFFFFF, m, off));
    if (lane == 0) red[w] = m;
    __syncthreads();
    float mmax = red[0];
    #pragma unroll
    for (int i = 1; i < 8; i++) mmax = fmaxf(mmax, red[i]);

    float p = (tid < T_LEN) ? __expf(v - mmax) : 0.0f;
    float ssum = p;
    #pragma unroll
    for (int off = 16; off > 0; off >>= 1)
        ssum += __shfl_xor_sync(0xFFFFFFFF, ssum, off);
    if (lane == 0) red[8 + w] = ssum;
    __syncthreads();
    float tot = red[8];
    #pragma unroll
    for (int i = 9; i < 16; i++) tot += red[i];
    float inv = 1.0f / tot;
    if (tid < ROWS) attnsh[tid] = p * inv;    // rows >= T_LEN get 0
    __syncthreads();

    // ---------------- out[b] = attn @ facts (smem-resident) ----------------
    {
        const int e = tid & 63;
        const int c = tid >> 6;                // 4 chunks of 52 rows
        float acc = 0.0f;
        const int t0 = c * 52;
        #pragma unroll 4
        for (int t = t0; t < t0 + 52; t++)
            acc = fmaf(attnsh[t], fsh[t * FS + e], acc);
        outred[c * 64 + e] = acc;
    }
    __syncthreads();
    if (tid < E_DIM)
        out[(size_t)b * E_DIM + tid] =
            outred[tid] + outred[64 + tid] + outred[128 + tid] + outred[192 + tid];
}

// ============================================================================
// launch
// ============================================================================
static inline size_t fused_smem_bytes() {
    size_t f = (size_t)ROWS * FS + 5120 + 3200 + H1 + H2 + H2 +
               ROWS + 16 + ROWS + NTHREADS + E_DIM;
    return f * sizeof(float);
}

extern "C" void kernel_launch(void* const* d_in, const int* in_sizes, int n_in,
                              void* d_out, int out_size)
{
    const float* query = (const float*)d_in[0];
    const float* facts = (const float*)d_in[1];
    const int*   mask  = (const int*)  d_in[2];
    const float* W1    = (const float*)d_in[3];
    const float* b1    = (const float*)d_in[4];
    const float* W2    = (const float*)d_in[5];
    const float* b2    = (const float*)d_in[6];
    const float* W3    = (const float*)d_in[7];
    float* out = (float*)d_out;

    const int B = in_sizes[0] / E_DIM;

    static bool configured = false;
    if (!configured) {
        cudaFuncSetAttribute(fused_kernel,
                             cudaFuncAttributeMaxDynamicSharedMemorySize,
                             (int)fused_smem_bytes());
        configured = true;
    }

    fused_kernel<<<B, NTHREADS, fused_smem_bytes()>>>(query, facts, mask,
                                                      W1, b1, W2, b2, W3, out);
}

// round 10
// speedup vs baseline: 1.0879x; 1.0879x over previous
#include <cuda_runtime.h>
#include <math.h>
#include <stdint.h>

#define T_LEN 200
#define E_DIM 64
#define H1 80
#define H2 40
#define NTHREADS 256
#define NSTRIPES 13        // 208 rows = 13 * 16 (covers T=200)
#define ROWS (16 * NSTRIPES)

#define FS 68              // facts tile stride [208][68]; float4-granule conflict-free

__device__ __forceinline__ float sigm(float x) {
    float t;
    asm("tanh.approx.f32 %0, %1;" : "=f"(t) : "f"(0.5f * x));
    return fmaf(0.5f, t, 0.5f);
}
__device__ __forceinline__ void mma_tf32(float c[4], const uint32_t a[4], const uint32_t b[2]) {
    asm volatile(
        "mma.sync.aligned.m16n8k8.row.col.f32.tf32.tf32.f32 "
        "{%0,%1,%2,%3}, {%4,%5,%6,%7}, {%8,%9}, {%0,%1,%2,%3};"
        : "+f"(c[0]), "+f"(c[1]), "+f"(c[2]), "+f"(c[3])
        : "r"(a[0]), "r"(a[1]), "r"(a[2]), "r"(a[3]), "r"(b[0]), "r"(b[1]));
}
__device__ __forceinline__ void cp_async16(uint32_t smem_addr, const void* gptr) {
    asm volatile("cp.async.cg.shared.global [%0], [%1], 16;" :: "r"(smem_addr), "l"(gptr));
}

// ============================================================================
// Single fused kernel: staging + per-batch weight transform + tensor-core MLP
// (h1 permuted so GEMM1's C-fragment == GEMM2's A-fragment; no exchange)
// + masked softmax + attn-weighted sum. One CTA per batch.
// ============================================================================
__global__ __launch_bounds__(NTHREADS, 2)
void fused_kernel(const float* __restrict__ query,
                  const float* __restrict__ facts,
                  const int*   __restrict__ mask,
                  const float* __restrict__ W1,
                  const float* __restrict__ b1,
                  const float* __restrict__ W2,
                  const float* __restrict__ b2,
                  const float* __restrict__ W3,
                  float* __restrict__ out)
{
    extern __shared__ float sm[];
    float* fsh     = sm;                  // [208][68] fp32
    float* wfr     = fsh + ROWS * FS;     // [5120] fragment-packed wefft (perm cols)
    float* w2fr    = wfr + 5120;          // [3200] fragment-packed W2
    float* c1sh    = w2fr + 3200;         // [80]  (logical unit order)
    float* b2sh    = c1sh + H1;           // [40]
    float* w3sh    = b2sh + H2;           // [40]
    float* scoresh = w3sh + H2;           // [208]
    float* red     = scoresh + ROWS;      // [16]
    float* attnsh  = red + 16;            // [208]
    float* outred  = attnsh + ROWS;       // [256]
    float* qsh     = outred + NTHREADS;   // [64]

    const int b    = blockIdx.x;
    const int tid  = threadIdx.x;
    const int w    = tid >> 5;
    const int lane = tid & 31;
    const int g    = lane >> 2;
    const int tg   = lane & 3;

    // ---------------- async facts staging: issue FIRST, consume later ----------
    {
        const float4* fb = (const float4*)(facts + (size_t)b * T_LEN * E_DIM);
        uint32_t fsh_base;
        asm("{ .reg .u64 t; cvta.to.shared.u64 t, %1; cvt.u32.u64 %0, t; }"
            : "=r"(fsh_base) : "l"(fsh));
        for (int i = tid; i < T_LEN * 16; i += NTHREADS) {
            int t = i >> 4, e4 = i & 15;
            cp_async16(fsh_base + (t * FS + e4 * 4) * 4, fb + i);
        }
        asm volatile("cp.async.commit_group;");
    }
    int mbit = 1;
    if (tid < T_LEN) mbit = mask[(size_t)b * T_LEN + tid];

    // zero pad rows [200,208)
    for (int i = tid; i < (ROWS - T_LEN) * 16; i += NTHREADS) {
        int t = T_LEN + (i >> 4), e4 = i & 15;
        *(float4*)&fsh[t * FS + e4 * 4] = make_float4(0.f, 0.f, 0.f, 0.f);
    }

    if (tid < E_DIM) qsh[tid] = query[(size_t)b * E_DIM + tid];
    if (tid < H2)    { b2sh[tid] = b2[tid]; w3sh[tid] = W3[tid]; }
    __syncthreads();    // qsh ready

    // ---------------- per-batch effective layer-1 weights (fragment-packed) ----
    // wefft[n][k] = W1[(64+k)*80+n] - W1[(128+k)*80+n] + q[k]*W1[(192+k)*80+n]
    // Column permutation within each 8-group: phys pos p holds logical unit
    // perm[p] = (p>>1) + (p&1)*4, so GEMM1 C-frag == GEMM2 A-frag.
    for (int fp = tid; fp < 2560; fp += NTHREADS) {
        int kt = fp / 320, rem = fp - kt * 320;
        int j = rem >> 5, l5 = rem & 31;
        int gg = l5 >> 2, tt = l5 & 3;
        int n = j * 8 + ((gg >> 1) + (gg & 1) * 4);   // permuted logical unit
        int ka = kt * 8 + tt, kb = ka + 4;
        float va = W1[(64 + ka) * H1 + n] - W1[(128 + ka) * H1 + n] + qsh[ka] * W1[(192 + ka) * H1 + n];
        float vb = W1[(64 + kb) * H1 + n] - W1[(128 + kb) * H1 + n] + qsh[kb] * W1[(192 + kb) * H1 + n];
        *(float2*)&wfr[2 * fp] = make_float2(va, vb);
    }
    // W2 fragments (identity k-order): pair = W2[(kt*8+tt)*40+n], W2[(kt*8+tt+4)*40+n]
    for (int fp = tid; fp < 1600; fp += NTHREADS) {
        int kt = fp / 160, rem = fp - kt * 160;
        int j = rem >> 5, l5 = rem & 31;
        int gg = l5 >> 2, tt = l5 & 3;
        int n = j * 8 + gg;
        int ka = kt * 8 + tt;
        *(float2*)&w2fr[2 * fp] = make_float2(W2[ka * H2 + n], W2[(ka + 4) * H2 + n]);
    }
    // c1 = b1 + q@(A+C)  (logical unit order)
    if (tid < H1) {
        float acc = b1[tid];
        #pragma unroll 8
        for (int e = 0; e < E_DIM; e++)
            acc += qsh[e] * (W1[e * H1 + tid] + W1[(128 + e) * H1 + tid]);
        c1sh[tid] = acc;
    }

    asm volatile("cp.async.wait_group 0;");
    __syncthreads();

    const uint32_t* fu = (const uint32_t*)fsh;

    // ---------------- per-stripe MLP (warp w handles stripes w, w+8) ------------
    for (int s = w; s < NSTRIPES; s += 8) {
        const int r0 = s * 16;

        // GEMM1: acc = F @ Weff^T (columns permuted within 8-groups)
        float acc[10][4];
        #pragma unroll
        for (int j = 0; j < 10; j++)
            #pragma unroll
            for (int q = 0; q < 4; q++) acc[j][q] = 0.0f;

        #pragma unroll
        for (int kt = 0; kt < 8; kt++) {
            const int k0 = kt * 8 + tg;
            uint32_t a[4];
            a[0] = fu[(r0 + g    ) * FS + k0    ];
            a[1] = fu[(r0 + g + 8) * FS + k0    ];
            a[2] = fu[(r0 + g    ) * FS + k0 + 4];
            a[3] = fu[(r0 + g + 8) * FS + k0 + 4];
            const float2* wp = (const float2*)wfr + kt * 320 + lane;
            #pragma unroll
            for (int j = 0; j < 10; j++) {
                float2 bw = wp[j * 32];
                uint32_t bf[2] = { __float_as_uint(bw.x), __float_as_uint(bw.y) };
                mma_tf32(acc[j], a, bf);
            }
        }

        // sigmoid + direct fragment renaming + GEMM2 (no shfl)
        // C-frag of GEMM1 j-group kt holds logical units: reg0/2 -> kt*8+tg
        // (rows g / g+8), reg1/3 -> kt*8+tg+4. A-frag wants exactly those.
        float acc2[5][4];
        #pragma unroll
        for (int j = 0; j < 5; j++)
            #pragma unroll
            for (int q = 0; q < 4; q++) acc2[j][q] = 0.0f;

        #pragma unroll
        for (int kt = 0; kt < 10; kt++) {
            const float c1a = c1sh[kt * 8 + tg];
            const float c1b = c1sh[kt * 8 + tg + 4];
            float h0 = sigm(acc[kt][0] + c1a);   // (row g,   unit tg)
            float h1v = sigm(acc[kt][1] + c1b);  // (row g,   unit tg+4)
            float h2v = sigm(acc[kt][2] + c1a);  // (row g+8, unit tg)
            float h3 = sigm(acc[kt][3] + c1b);   // (row g+8, unit tg+4)

            uint32_t a[4] = { __float_as_uint(h0), __float_as_uint(h2v),
                              __float_as_uint(h1v), __float_as_uint(h3) };
            const float2* wp2 = (const float2*)w2fr + kt * 160 + lane;
            #pragma unroll
            for (int j = 0; j < 5; j++) {
                float2 bw = wp2[j * 32];
                uint32_t bf[2] = { __float_as_uint(bw.x), __float_as_uint(bw.y) };
                mma_tf32(acc2[j], a, bf);
            }
        }

        // epilogue: sigmoid, dot W3, quad-reduce, scores -> smem
        float s_lo = 0.0f, s_hi = 0.0f;
        #pragma unroll
        for (int j = 0; j < 5; j++) {
            const int n0 = j * 8 + 2 * tg;
            float bb0 = b2sh[n0], bb1 = b2sh[n0 + 1];
            float w30 = w3sh[n0], w31 = w3sh[n0 + 1];
            s_lo += sigm(acc2[j][0] + bb0) * w30 + sigm(acc2[j][1] + bb1) * w31;
            s_hi += sigm(acc2[j][2] + bb0) * w30 + sigm(acc2[j][3] + bb1) * w31;
        }
        s_lo += __shfl_xor_sync(0xFFFFFFFF, s_lo, 1);
        s_lo += __shfl_xor_sync(0xFFFFFFFF, s_lo, 2);
        s_hi += __shfl_xor_sync(0xFFFFFFFF, s_hi, 1);
        s_hi += __shfl_xor_sync(0xFFFFFFFF, s_hi, 2);

        if (tg == 0) {   // b3 omitted: constant shift cancels in softmax
            scoresh[r0 + g]     = s_lo;
            scoresh[r0 + g + 8] = s_hi;
        }
    }
    __syncthreads();

    // ---------------- masked softmax over T (warp-shuffle reductions) ----------
    const float PADV = -4294967295.0f;   // -2^32 + 1
    float v;
    if (tid < T_LEN)
        v = (mbit == 1) ? scoresh[tid] : PADV;
    else
        v = -INFINITY;

    float m = v;
    #pragma unroll
    for (int off = 16; off > 0; off >>= 1)
        m = fmaxf(m, __shfl_xor_sync(0xFFFFFFFF, m, off));
    if (lane == 0) red[w] = m;
    __syncthreads();
    float mmax = red[0];
    #pragma unroll
    for (int i = 1; i < 8; i++) mmax = fmaxf(mmax, red[i]);

    float p = (tid < T_LEN) ? __expf(v - mmax) : 0.0f;
    float ssum = p;
    #pragma unroll
    for (int off = 16; off > 0; off >>= 1)
        ssum += __shfl_xor_sync(0xFFFFFFFF, ssum, off);
    if (lane == 0) red[8 + w] = ssum;
    __syncthreads();
    float tot = red[8];
    #pragma unroll
    for (int i = 9; i < 16; i++) tot += red[i];
    float inv = 1.0f / tot;
    if (tid < ROWS) attnsh[tid] = p * inv;    // rows >= T_LEN get 0
    __syncthreads();

    // ---------------- out[b] = attn @ facts (smem-resident) ----------------
    {
        const int e = tid & 63;
        const int c = tid >> 6;                // 4 chunks of 52 rows
        float acc = 0.0f;
        const int t0 = c * 52;
        #pragma unroll 4
        for (int t = t0; t < t0 + 52; t++)
            acc = fmaf(attnsh[t], fsh[t * FS + e], acc);
        outred[c * 64 + e] = acc;
    }
    __syncthreads();
    if (tid < E_DIM)
        out[(size_t)b * E_DIM + tid] =
            outred[tid] + outred[64 + tid] + outred[128 + tid] + outred[192 + tid];
}

// ============================================================================
// launch
// ============================================================================
static inline size_t fused_smem_bytes() {
    size_t f = (size_t)ROWS * FS + 5120 + 3200 + H1 + H2 + H2 +
               ROWS + 16 + ROWS + NTHREADS + E_DIM;
    return f * sizeof(float);
}

extern "C" void kernel_launch(void* const* d_in, const int* in_sizes, int n_in,
                              void* d_out, int out_size)
{
    const float* query = (const float*)d_in[0];
    const float* facts = (const float*)d_in[1];
    const int*   mask  = (const int*)  d_in[2];
    const float* W1    = (const float*)d_in[3];
    const float* b1    = (const float*)d_in[4];
    const float* W2    = (const float*)d_in[5];
    const float* b2    = (const float*)d_in[6];
    const float* W3    = (const float*)d_in[7];
    float* out = (float*)d_out;

    const int B = in_sizes[0] / E_DIM;

    static bool configured = false;
    if (!configured) {
        cudaFuncSetAttribute(fused_kernel,
                             cudaFuncAttributeMaxDynamicSharedMemorySize,
                             (int)fused_smem_bytes());
        configured = true;
    }

    fused_kernel<<<B, NTHREADS, fused_smem_bytes()>>>(query, facts, mask,
                                                      W1, b1, W2, b2, W3, out);
}